// round 12
// baseline (speedup 1.0000x reference)
#include <cuda_runtime.h>
#include <cuda_bf16.h>
#include <math.h>

// ============================================================================
// HamGNNInspiredNodeBlock: FullyConnectedTensorProduct(x,x) + o3.Linear skip
// irreps = 32x0e + 32x1o + 16x2e  (dims 32 + 96 + 80 = 208), 200000 nodes
// ============================================================================

#define NNODES   200000
#define TOTDIM   208
#define TN       32          // nodes per CTA (lane = node)
#define NTHREADS 256
#define NBLOCKS  (NNODES / TN)   // 6250 exactly
#define CU       28          // uv-chunk size (sized so smem fits 48KB static)
#define TPWSIZE  208896
#define LNWSIZE  2304

// smem layout (floats)
#define XS_SZ (TOTDIM * TN)        // 6656  x staged as [feat][node]
#define AS_SZ (CU * 5 * TN)        // 4480  A chunk [c][k(pad 5)][node]
#define WS_SZ (CU * 32)            // 896   W chunk [c][wo]

struct Ent { int code; float val; };   // code = i | (j<<3); k implied by ordering

#define NKEYS 11
__constant__ int c_keyL[NKEYS][3] = {
  {0,0,0},{0,1,1},{0,2,2},{1,0,1},{1,1,0},{1,1,2},
  {1,2,1},{2,0,2},{2,1,1},{2,2,0},{2,2,2}};
__constant__ int c_outK[NKEYS] = {0,1,2,1,0,2,1,2,1,0,2};

__device__ double d_wtmp[NKEYS][125];       // raw real w3j (un-normalized)
__device__ Ent    g_ents[NKEYS * 128];      // sparse entries, sorted by output m (k)
__device__ int    g_entCntK[NKEYS * 5];     // per-path per-k entry counts

// ---------------------------------------------------------------------------
// init kernel: build real-basis wigner-3j sparse tables (mirrors reference)
// ---------------------------------------------------------------------------
__device__ double dev_cg(int j1,int m1,int j2,int m2,int j3,int m3)
{
  if (m1 + m2 != m3) return 0.0;
  double f[8]; f[0]=1.0;
  for (int i=1;i<8;i++) f[i]=f[i-1]*(double)i;
  double pref = sqrt((2.0*j3+1.0)*f[j3+j1-j2]*f[j3-j1+j2]*f[j1+j2-j3]/f[j1+j2+j3+1]);
  pref *= sqrt(f[j3+m3]*f[j3-m3]*f[j1-m1]*f[j1+m1]*f[j2-m2]*f[j2+m2]);
  int kmin = 0;
  if (j2-j3-m1 > kmin) kmin = j2-j3-m1;
  if (j1-j3+m2 > kmin) kmin = j1-j3+m2;
  int kmax = j1+j2-j3;
  if (j1-m1 < kmax) kmax = j1-m1;
  if (j2+m2 < kmax) kmax = j2+m2;
  double s = 0.0;
  for (int k=kmin;k<=kmax;k++){
    double d = f[k]*f[j1+j2-j3-k]*f[j1-m1-k]*f[j2+m2-k]*f[j3-j2+m1+k]*f[j3-j1-m2+k];
    s += ((k&1)? -1.0 : 1.0)/d;
  }
  return pref*s;
}

__device__ void dev_q(int l, double qr[5][5], double qi[5][5])
{
  for (int a=0;a<5;a++) for (int b=0;b<5;b++){ qr[a][b]=0.0; qi[a][b]=0.0; }
  double s = 1.0/sqrt(2.0);
  for (int m=-l; m<0; m++){           // row l+m: q[., l-m]=s ; q[., l+m]=-i*s
    qr[l+m][l-m] = s;
    qi[l+m][l+m] = -s;
  }
  qr[l][l] = 1.0;
  for (int m=1; m<=l; m++){           // row l+m: q[., l+m]=sg*s ; q[., l-m]=i*sg*s
    double sg = (m&1)? -1.0 : 1.0;
    qr[l+m][l+m] = sg*s;
    qi[l+m][l-m] = sg*s;
  }
  // multiply by (-i)^l
  double pr, pi;
  switch (l & 3){
    case 0: pr=1.0;  pi=0.0;  break;
    case 1: pr=0.0;  pi=-1.0; break;
    case 2: pr=-1.0; pi=0.0;  break;
    default:pr=0.0;  pi=1.0;  break;
  }
  for (int a=0;a<5;a++) for (int b=0;b<5;b++){
    double r=qr[a][b], im=qi[a][b];
    qr[a][b] = r*pr - im*pi;
    qi[a][b] = r*pi + im*pr;
  }
}

__global__ void initK()
{
  int tid = threadIdx.x;
  // phase 1: every real-basis w3j element in parallel
  for (int idx = tid; idx < NKEYS*125; idx += blockDim.x){
    int p = idx/125, r = idx%125;
    int l1=c_keyL[p][0], l2=c_keyL[p][1], l3=c_keyL[p][2];
    int d1=2*l1+1, d2=2*l2+1, d3=2*l3+1;
    int i=r/25, j=(r/5)%5, k=r%5;
    double val = 0.0;
    if (i<d1 && j<d2 && k<d3){
      double q1r[5][5],q1i[5][5],q2r[5][5],q2i[5][5],q3r[5][5],q3i[5][5];
      dev_q(l1,q1r,q1i); dev_q(l2,q2r,q2i); dev_q(l3,q3r,q3i);
      for (int a=0;a<d1;a++){
        for (int b=0;b<d2;b++){
          int m1=a-l1, m2=b-l2, m3=m1+m2;
          if (m3 < -l3 || m3 > l3) continue;
          double C = dev_cg(l1,m1,l2,m2,l3,m3);
          if (C == 0.0) continue;
          int c = m3+l3;
          double tr = q1r[a][i]*q2r[b][j] - q1i[a][i]*q2i[b][j];
          double ti = q1r[a][i]*q2i[b][j] + q1i[a][i]*q2r[b][j];
          // t * conj(q3[c][k])
          double ur = tr*q3r[c][k] + ti*q3i[c][k];
          val += ur*C;
        }
      }
    }
    d_wtmp[p][r] = val;
  }
  __syncthreads();
  // phase 2: normalize (unit Frobenius), fold e3nn path coeff, emit sparse
  if (tid < NKEYS){
    int p = tid;
    double nrm = 0.0;
    for (int r=0;r<125;r++) nrm += d_wtmp[p][r]*d_wtmp[p][r];
    nrm = sqrt(nrm);
    // PATH_COEFF = sqrt((2*l3+1)/FAN[k_out]); FAN = {2304, 3072, 2304}
    double coeff[3] = { sqrt(1.0/2304.0), sqrt(3.0/3072.0), sqrt(5.0/2304.0) };
    double cf = coeff[c_outK[p]] / nrm;
    int l1=c_keyL[p][0], l2=c_keyL[p][1], l3=c_keyL[p][2];
    int d1=2*l1+1, d2=2*l2+1, d3=2*l3+1;
    int cnt = 0;
    for (int k=0;k<d3;k++){
      int ck = 0;
      for (int i=0;i<d1;i++){
        for (int j=0;j<d2;j++){
          double v = d_wtmp[p][i*25 + j*5 + k];
          if (fabs(v) > 1e-9*nrm){
            Ent e; e.code = i | (j<<3); e.val = (float)(v*cf);
            g_ents[p*128 + cnt] = e; cnt++; ck++;
          }
        }
      }
      g_entCntK[p*5 + k] = ck;
    }
    for (int k=d3;k<5;k++) g_entCntK[p*5 + k] = 0;
  }
}

// ---------------------------------------------------------------------------
// main kernel
// ---------------------------------------------------------------------------
// warp roles (accumulator ownership, lane = node):
//   warps 0,1 : irrep0, 16 channels each, kd=1   acc[0..15]
//   warps 2-5 : irrep1,  8 channels each, kd=3   acc[ch*3+k]
//   warps 6,7 : irrep2,  8 channels each, kd=5   acc[ch*5+k]

template<int UVC,int M2SH,int D1,int D2,int OFF1,int OFF2,int PK,int KD,int M3,bool LIN>
__device__ __forceinline__
void doPath(const float* __restrict__ xs, float* __restrict__ As, float* __restrict__ Ws,
            const float* __restrict__ wsrc, int slot, float linScale,
            int warp, int lane, int tid, int myIrrep, int woBase, float* acc)
{
  int cnts[KD]; int bases[KD];
  if constexpr (!LIN){
    int b = 0;
    #pragma unroll
    for (int k=0;k<KD;k++){ cnts[k] = g_entCntK[slot*5+k]; bases[k] = b; b += cnts[k]; }
  } else {
    #pragma unroll
    for (int k=0;k<KD;k++){ cnts[k]=0; bases[k]=0; }
  }

  for (int uv0 = 0; uv0 < UVC; uv0 += CU){
    const int cNum = (UVC - uv0 < CU) ? (UVC - uv0) : CU;

    // ---- A-gen: warp handles c = warp, warp+8, ... ; lane = node ----
    for (int c = warp; c < cNum; c += 8){
      int uv = uv0 + c;
      float a[KD];
      if constexpr (LIN){
        #pragma unroll
        for (int k=0;k<KD;k++)
          a[k] = xs[(OFF1 + uv*D1 + k)*TN + lane] * linScale;
      } else {
        int u = uv >> M2SH;
        int v = uv & ((1<<M2SH)-1);
        const float* x1 = xs + (OFF1 + u*D1)*TN + lane;
        const float* x2 = xs + (OFF2 + v*D2)*TN + lane;
        const Ent* ep = g_ents + slot*128;
        #pragma unroll
        for (int k=0;k<KD;k++){
          float s = 0.f;
          int cnt = cnts[k], base = bases[k];
          for (int t=0;t<cnt;t++){
            Ent e = ep[base + t];
            int i = e.code & 7, j = (e.code >> 3) & 7;
            s += e.val * x1[i*TN] * x2[j*TN];
          }
          a[k] = s;
        }
      }
      #pragma unroll
      for (int k=0;k<KD;k++) As[(c*5+k)*TN + lane] = a[k];
    }

    // ---- W chunk load: layout [c][wo] contiguous in gmem ----
    {
      const float* wp = wsrc + uv0*M3;
      int total = cNum * M3;
      for (int idx = tid; idx < total; idx += NTHREADS) Ws[idx] = wp[idx];
    }
    __syncthreads();

    // ---- accumulate (warps owning this output irrep) ----
    if (myIrrep == PK){
      const int NCH = (KD==1) ? 16 : 8;
      for (int c=0;c<cNum;c++){
        float av[KD];
        #pragma unroll
        for (int k=0;k<KD;k++) av[k] = As[(c*5+k)*TN + lane];
        const float* wrow = Ws + c*M3 + woBase;
        #pragma unroll
        for (int ch=0; ch<NCH; ch++){
          float wv = wrow[ch];
          #pragma unroll
          for (int k=0;k<KD;k++) acc[ch*KD + k] += wv * av[k];
        }
      }
    }
    __syncthreads();
  }
}

__global__ void __launch_bounds__(NTHREADS)
mainK(const float* __restrict__ x, const float* __restrict__ tpw,
      const float* __restrict__ lnw, float* __restrict__ out)
{
  __shared__ float xs[XS_SZ];
  __shared__ float As[AS_SZ];
  __shared__ float Ws[WS_SZ];

  int tid  = threadIdx.x;
  int lane = tid & 31;
  int warp = tid >> 5;
  int node0 = blockIdx.x * TN;

  // stage x transposed: xs[f][node]
  for (int idx = tid; idx < XS_SZ; idx += NTHREADS){
    int n = idx / TOTDIM, f = idx % TOTDIM;
    xs[f*TN + n] = x[(node0 + n)*TOTDIM + f];
  }
  __syncthreads();

  float acc[40];
  #pragma unroll
  for (int i=0;i<40;i++) acc[i] = 0.f;

  int myIrrep, woBase;
  if      (warp < 2){ myIrrep = 0; woBase = warp*16; }
  else if (warp < 6){ myIrrep = 1; woBase = (warp-2)*8; }
  else              { myIrrep = 2; woBase = (warp-6)*8; }

  // ---- 11 tensor-product paths ----
  // weight sizes: p0 32768, p1 32768, p2 8192, p3 32768, p4 32768, p5 16384,
  //               p6 16384, p7 8192, p8 16384, p9 8192, p10 4096  (total 208896)
  //      <UVC, M2SH, D1, D2, OFF1, OFF2, PK, KD, M3, LIN>
  doPath<1024,5,1,1,  0,  0, 0,1,32,false>(xs,As,Ws, tpw+0,      0, 0.f, warp,lane,tid,myIrrep,woBase,acc);
  doPath<1024,5,1,3,  0, 32, 1,3,32,false>(xs,As,Ws, tpw+32768,  1, 0.f, warp,lane,tid,myIrrep,woBase,acc);
  doPath< 512,4,1,5,  0,128, 2,5,16,false>(xs,As,Ws, tpw+65536,  2, 0.f, warp,lane,tid,myIrrep,woBase,acc);
  doPath<1024,5,3,1, 32,  0, 1,3,32,false>(xs,As,Ws, tpw+73728,  3, 0.f, warp,lane,tid,myIrrep,woBase,acc);
  doPath<1024,5,3,3, 32, 32, 0,1,32,false>(xs,As,Ws, tpw+106496, 4, 0.f, warp,lane,tid,myIrrep,woBase,acc);
  doPath<1024,5,3,3, 32, 32, 2,5,16,false>(xs,As,Ws, tpw+139264, 5, 0.f, warp,lane,tid,myIrrep,woBase,acc);
  doPath< 512,4,3,5, 32,128, 1,3,32,false>(xs,As,Ws, tpw+155648, 6, 0.f, warp,lane,tid,myIrrep,woBase,acc);
  doPath< 512,5,5,1,128,  0, 2,5,16,false>(xs,As,Ws, tpw+172032, 7, 0.f, warp,lane,tid,myIrrep,woBase,acc);
  doPath< 512,5,5,3,128, 32, 1,3,32,false>(xs,As,Ws, tpw+180224, 8, 0.f, warp,lane,tid,myIrrep,woBase,acc);
  doPath< 256,4,5,5,128,128, 0,1,32,false>(xs,As,Ws, tpw+196608, 9, 0.f, warp,lane,tid,myIrrep,woBase,acc);
  doPath< 256,4,5,5,128,128, 2,5,16,false>(xs,As,Ws, tpw+204800,10, 0.f, warp,lane,tid,myIrrep,woBase,acc);

  // ---- linear skip paths: out += einsum('uw,zui->zwi', W, seg)/sqrt(m) ----
  doPath<  32,0,1,1,  0,  0, 0,1,32,true >(xs,As,Ws, lnw+0,     0, 0.17677669529663689f, warp,lane,tid,myIrrep,woBase,acc);
  doPath<  32,0,3,1, 32,  0, 1,3,32,true >(xs,As,Ws, lnw+1024,  0, 0.17677669529663689f, warp,lane,tid,myIrrep,woBase,acc);
  doPath<  16,0,5,1,128,  0, 2,5,16,true >(xs,As,Ws, lnw+2048,  0, 0.25f,                warp,lane,tid,myIrrep,woBase,acc);

  // ---- stage outputs through smem transpose for coalesced store ----
  if (myIrrep == 0){
    #pragma unroll
    for (int ch=0; ch<16; ch++)
      xs[(woBase+ch)*TN + lane] = acc[ch];
  } else if (myIrrep == 1){
    #pragma unroll
    for (int ch=0; ch<8; ch++)
      #pragma unroll
      for (int k=0;k<3;k++)
        xs[(32 + (woBase+ch)*3 + k)*TN + lane] = acc[ch*3+k];
  } else {
    #pragma unroll
    for (int ch=0; ch<8; ch++)
      #pragma unroll
      for (int k=0;k<5;k++)
        xs[(128 + (woBase+ch)*5 + k)*TN + lane] = acc[ch*5+k];
  }
  __syncthreads();
  for (int idx = tid; idx < XS_SZ; idx += NTHREADS){
    int n = idx / TOTDIM, f = idx % TOTDIM;
    out[(node0 + n)*TOTDIM + f] = xs[f*TN + n];
  }
}

// ---------------------------------------------------------------------------
extern "C" void kernel_launch(void* const* d_in, const int* in_sizes, int n_in,
                              void* d_out, int out_size)
{
  // identify inputs by element count (x, tp_w, lin_w)
  const float* x   = (const float*)d_in[0];
  const float* tpw = (n_in > 1) ? (const float*)d_in[1] : nullptr;
  const float* lnw = (n_in > 2) ? (const float*)d_in[2] : nullptr;
  for (int i=0;i<n_in;i++){
    if      (in_sizes[i] == NNODES*TOTDIM) x   = (const float*)d_in[i];
    else if (in_sizes[i] == TPWSIZE)       tpw = (const float*)d_in[i];
    else if (in_sizes[i] == LNWSIZE)       lnw = (const float*)d_in[i];
  }

  initK<<<1, 256>>>();
  mainK<<<NBLOCKS, NTHREADS>>>(x, tpw, lnw, (float*)d_out);
}

// round 14
// speedup vs baseline: 1.7269x; 1.7269x over previous
#include <cuda_runtime.h>
#include <math.h>

// ============================================================================
// HamGNNInspiredNodeBlock: FullyConnectedTensorProduct(x,x) + o3.Linear skip
// irreps = 32x0e + 32x1o + 16x2e  (dims 32 + 96 + 80 = 208), 200000 nodes
// Packed 2-nodes-per-lane (f32x2), balanced 8-way channel ownership.
// ============================================================================

#define NNODES   200000
#define TOTDIM   208
#define TN       64          // nodes per CTA (lane holds nodes lane & lane+32 packed)
#define NTHREADS 256
#define NBLOCKS  (NNODES / TN)   // 3125 exactly
#define CU       28          // uv-chunk size
#define TPWSIZE  208896
#define LNWSIZE  2304
#define EPS_SLOT 80          // staged entries per path slot (actual nnz <= ~44)

// dynamic smem partition (float2 counts)
#define XS2_N (TOTDIM * 32)   // 6656 float2 = 53248 B   x staged [feat][lane] packed
#define AS2_N (CU * 5 * 32)   // 4480 float2 = 35840 B   A chunk [c][k(pad5)][lane]
#define WS2_N (CU * 32)       //  896 float2 =  7168 B   W chunk duplicated (w,w)
#define SMEM_DYN ((XS2_N + AS2_N + WS2_N) * 8 + 11 * EPS_SLOT * 16)   // 110336 B

struct Ent { int code; float val; };   // code = i | (j<<3)

#define NKEYS 11
__constant__ int c_keyL[NKEYS][3] = {
  {0,0,0},{0,1,1},{0,2,2},{1,0,1},{1,1,0},{1,1,2},
  {1,2,1},{2,0,2},{2,1,1},{2,2,0},{2,2,2}};
__constant__ int c_outK[NKEYS] = {0,1,2,1,0,2,1,2,1,0,2};

__device__ double d_wtmp[NKEYS][125];       // raw real w3j (un-normalized)
__device__ Ent    g_ents[NKEYS * 128];      // sparse entries, sorted by output m (k)
__device__ int    g_entCntK[NKEYS * 5];     // per-path per-k entry counts

// ---------------------------------------------------------------------------
// packed f32x2 helpers
// ---------------------------------------------------------------------------
union F2U { float2 f; unsigned long long u; };

__device__ __forceinline__ float2 f2fma(float2 a, float2 b, float2 c){
  F2U A, B, C, D; A.f = a; B.f = b; C.f = c;
  asm("fma.rn.f32x2 %0, %1, %2, %3;" : "=l"(D.u) : "l"(A.u), "l"(B.u), "l"(C.u));
  return D.f;
}
__device__ __forceinline__ float2 f2mul(float2 a, float2 b){
  F2U A, B, D; A.f = a; B.f = b;
  asm("mul.rn.f32x2 %0, %1, %2;" : "=l"(D.u) : "l"(A.u), "l"(B.u));
  return D.f;
}

// ---------------------------------------------------------------------------
// init kernel: build real-basis wigner-3j sparse tables (mirrors reference)
// ---------------------------------------------------------------------------
__device__ double dev_cg(int j1,int m1,int j2,int m2,int j3,int m3)
{
  if (m1 + m2 != m3) return 0.0;
  double f[8]; f[0]=1.0;
  for (int i=1;i<8;i++) f[i]=f[i-1]*(double)i;
  double pref = sqrt((2.0*j3+1.0)*f[j3+j1-j2]*f[j3-j1+j2]*f[j1+j2-j3]/f[j1+j2+j3+1]);
  pref *= sqrt(f[j3+m3]*f[j3-m3]*f[j1-m1]*f[j1+m1]*f[j2-m2]*f[j2+m2]);
  int kmin = 0;
  if (j2-j3-m1 > kmin) kmin = j2-j3-m1;
  if (j1-j3+m2 > kmin) kmin = j1-j3+m2;
  int kmax = j1+j2-j3;
  if (j1-m1 < kmax) kmax = j1-m1;
  if (j2+m2 < kmax) kmax = j2+m2;
  double s = 0.0;
  for (int k=kmin;k<=kmax;k++){
    double d = f[k]*f[j1+j2-j3-k]*f[j1-m1-k]*f[j2+m2-k]*f[j3-j2+m1+k]*f[j3-j1-m2+k];
    s += ((k&1)? -1.0 : 1.0)/d;
  }
  return pref*s;
}

__device__ void dev_q(int l, double qr[5][5], double qi[5][5])
{
  for (int a=0;a<5;a++) for (int b=0;b<5;b++){ qr[a][b]=0.0; qi[a][b]=0.0; }
  double s = 1.0/sqrt(2.0);
  for (int m=-l; m<0; m++){
    qr[l+m][l-m] = s;
    qi[l+m][l+m] = -s;
  }
  qr[l][l] = 1.0;
  for (int m=1; m<=l; m++){
    double sg = (m&1)? -1.0 : 1.0;
    qr[l+m][l+m] = sg*s;
    qi[l+m][l-m] = sg*s;
  }
  double pr, pi;
  switch (l & 3){
    case 0: pr=1.0;  pi=0.0;  break;
    case 1: pr=0.0;  pi=-1.0; break;
    case 2: pr=-1.0; pi=0.0;  break;
    default:pr=0.0;  pi=1.0;  break;
  }
  for (int a=0;a<5;a++) for (int b=0;b<5;b++){
    double r=qr[a][b], im=qi[a][b];
    qr[a][b] = r*pr - im*pi;
    qi[a][b] = r*pi + im*pr;
  }
}

__global__ void initK()
{
  int tid = threadIdx.x;
  for (int idx = tid; idx < NKEYS*125; idx += blockDim.x){
    int p = idx/125, r = idx%125;
    int l1=c_keyL[p][0], l2=c_keyL[p][1], l3=c_keyL[p][2];
    int d1=2*l1+1, d2=2*l2+1, d3=2*l3+1;
    int i=r/25, j=(r/5)%5, k=r%5;
    double val = 0.0;
    if (i<d1 && j<d2 && k<d3){
      double q1r[5][5],q1i[5][5],q2r[5][5],q2i[5][5],q3r[5][5],q3i[5][5];
      dev_q(l1,q1r,q1i); dev_q(l2,q2r,q2i); dev_q(l3,q3r,q3i);
      for (int a=0;a<d1;a++){
        for (int b=0;b<d2;b++){
          int m1=a-l1, m2=b-l2, m3=m1+m2;
          if (m3 < -l3 || m3 > l3) continue;
          double C = dev_cg(l1,m1,l2,m2,l3,m3);
          if (C == 0.0) continue;
          int c = m3+l3;
          double tr = q1r[a][i]*q2r[b][j] - q1i[a][i]*q2i[b][j];
          double ti = q1r[a][i]*q2i[b][j] + q1i[a][i]*q2r[b][j];
          double ur = tr*q3r[c][k] + ti*q3i[c][k];
          val += ur*C;
        }
      }
    }
    d_wtmp[p][r] = val;
  }
  __syncthreads();
  if (tid < NKEYS){
    int p = tid;
    double nrm = 0.0;
    for (int r=0;r<125;r++) nrm += d_wtmp[p][r]*d_wtmp[p][r];
    nrm = sqrt(nrm);
    double coeff[3] = { sqrt(1.0/2304.0), sqrt(3.0/3072.0), sqrt(5.0/2304.0) };
    double cf = coeff[c_outK[p]] / nrm;
    int l1=c_keyL[p][0], l2=c_keyL[p][1], l3=c_keyL[p][2];
    int d1=2*l1+1, d2=2*l2+1, d3=2*l3+1;
    int cnt = 0;
    for (int k=0;k<d3;k++){
      int ck = 0;
      for (int i=0;i<d1;i++){
        for (int j=0;j<d2;j++){
          double v = d_wtmp[p][i*25 + j*5 + k];
          if (fabs(v) > 1e-9*nrm){
            Ent e; e.code = i | (j<<3); e.val = (float)(v*cf);
            g_ents[p*128 + cnt] = e; cnt++; ck++;
          }
        }
      }
      g_entCntK[p*5 + k] = ck;
    }
    for (int k=d3;k<5;k++) g_entCntK[p*5 + k] = 0;
  }
}

// ---------------------------------------------------------------------------
// main kernel: one path = chunked A-gen + W-stage + balanced accumulate
// ---------------------------------------------------------------------------
// channel ownership (EVERY warp owns a slice of EVERY output irrep):
//   irrep0: warp w owns ch [4w, 4w+4)   -> acc0[4]
//   irrep1: warp w owns ch [4w, 4w+4)   -> acc1[4][3]
//   irrep2: warp w owns ch [2w, 2w+2)   -> acc2[2][5]

template<int UVC,int M2SH,int D1,int D2,int OFF1,int OFF2,int KD,int M3,bool LIN>
__device__ __forceinline__
void doPath(const float2* __restrict__ xs2, float2* __restrict__ As2,
            float2* __restrict__ Ws2, const int4* __restrict__ entsS,
            const float* __restrict__ wsrc, int slot, float linScale,
            int warp, int lane, int tid, float2* __restrict__ acc)
{
  const int NCHW = (M3 == 16) ? 2 : 4;
  const int woBase = warp * NCHW;

  int cnts[KD]; int bases[KD];
  if constexpr (!LIN){
    int b = 0;
    #pragma unroll
    for (int k=0;k<KD;k++){ cnts[k] = g_entCntK[slot*5+k]; bases[k] = b; b += cnts[k]; }
  } else {
    #pragma unroll
    for (int k=0;k<KD;k++){ cnts[k]=0; bases[k]=0; }
  }

  for (int uv0 = 0; uv0 < UVC; uv0 += CU){
    const int cNum = (UVC - uv0 < CU) ? (UVC - uv0) : CU;

    // ---- A-gen: warp handles c = warp, warp+8, ... ; lane = node-pair ----
    for (int c = warp; c < cNum; c += 8){
      int uv = uv0 + c;
      float2 a[KD];
      if constexpr (LIN){
        #pragma unroll
        for (int k=0;k<KD;k++){
          float2 t = xs2[(OFF1 + uv*D1 + k)*32 + lane];
          a[k] = make_float2(t.x*linScale, t.y*linScale);
        }
      } else {
        int u = uv >> M2SH;
        int v = uv & ((1<<M2SH)-1);
        const char* x1b = (const char*)(xs2 + (OFF1 + u*D1)*32 + lane);
        const char* x2b = (const char*)(xs2 + (OFF2 + v*D2)*32 + lane);
        const int4* ep = entsS + slot*EPS_SLOT;
        #pragma unroll
        for (int k=0;k<KD;k++){
          float2 s = make_float2(0.f, 0.f);
          int cnt = cnts[k], base = bases[k];
          for (int t=0;t<cnt;t++){
            int4 e = ep[base + t];            // LDS.128 broadcast
            float2 a1 = *(const float2*)(x1b + e.x);
            float2 a2 = *(const float2*)(x2b + e.y);
            float2 vv; vv.x = __int_as_float(e.z); vv.y = __int_as_float(e.w);
            s = f2fma(f2mul(a1, a2), vv, s);
          }
          a[k] = s;
        }
      }
      #pragma unroll
      for (int k=0;k<KD;k++) As2[(c*5+k)*32 + lane] = a[k];
    }

    // ---- W chunk load, duplicated (w,w) for packed FMA ----
    {
      const float* wp = wsrc + uv0*M3;
      int total = cNum * M3;
      for (int idx = tid; idx < total; idx += NTHREADS){
        float w = wp[idx];
        Ws2[idx] = make_float2(w, w);
      }
    }
    __syncthreads();

    // ---- accumulate: ALL warps, each its channel slice ----
    #pragma unroll 2
    for (int c=0;c<cNum;c++){
      float2 av[KD];
      #pragma unroll
      for (int k=0;k<KD;k++) av[k] = As2[(c*5+k)*32 + lane];
      const float4* w4 = (const float4*)(Ws2 + c*M3 + woBase);
      #pragma unroll
      for (int cp=0; cp<NCHW/2; cp++){
        float4 wp4 = w4[cp];                  // (w0,w0,w1,w1) broadcast
        float2 wa; wa.x = wp4.x; wa.y = wp4.y;
        float2 wb; wb.x = wp4.z; wb.y = wp4.w;
        #pragma unroll
        for (int k=0;k<KD;k++){
          acc[(2*cp  )*KD + k] = f2fma(av[k], wa, acc[(2*cp  )*KD + k]);
          acc[(2*cp+1)*KD + k] = f2fma(av[k], wb, acc[(2*cp+1)*KD + k]);
        }
      }
    }
    __syncthreads();
  }
}

__global__ void __launch_bounds__(NTHREADS, 2)
mainK(const float* __restrict__ x, const float* __restrict__ tpw,
      const float* __restrict__ lnw, float* __restrict__ out)
{
  extern __shared__ char smRaw[];
  float2* xs2   = (float2*)smRaw;            // [feat][lane] packed node-pairs
  float2* As2   = xs2 + XS2_N;
  float2* Ws2   = As2 + AS2_N;
  int4*   entsS = (int4*)(Ws2 + WS2_N);      // 16B entries: off1B, off2B, val, val

  int tid  = threadIdx.x;
  int lane = tid & 31;
  int warp = tid >> 5;
  int node0 = blockIdx.x * TN;

  // stage sparse entries into smem with pre-scaled byte offsets
  for (int idx = tid; idx < NKEYS*EPS_SLOT; idx += NTHREADS){
    int s = idx / EPS_SLOT, t = idx % EPS_SLOT;
    Ent e = g_ents[s*128 + t];
    int i = e.code & 7, j = (e.code >> 3) & 7;
    entsS[idx] = make_int4(i*256, j*256, __float_as_int(e.val), __float_as_int(e.val));
  }

  // stage x packed: node n -> lane n&31, component n>>5
  float* xf = (float*)xs2;
  for (int idx = tid; idx < TN*TOTDIM; idx += NTHREADS){
    int n = idx / TOTDIM, f = idx % TOTDIM;
    xf[(f*32 + (n & 31))*2 + (n >> 5)] = x[(node0 + n)*TOTDIM + f];
  }
  __syncthreads();

  float2 acc0[4], acc1[12], acc2[10];
  #pragma unroll
  for (int i=0;i<4;i++)  acc0[i] = make_float2(0.f,0.f);
  #pragma unroll
  for (int i=0;i<12;i++) acc1[i] = make_float2(0.f,0.f);
  #pragma unroll
  for (int i=0;i<10;i++) acc2[i] = make_float2(0.f,0.f);

  // ---- 11 tensor-product paths (weight offsets cumulative over true sizes) ----
  //      <UVC, M2SH, D1, D2, OFF1, OFF2, KD, M3, LIN>
  doPath<1024,5,1,1,  0,  0,1,32,false>(xs2,As2,Ws2,entsS, tpw+0,      0, 0.f, warp,lane,tid, acc0);
  doPath<1024,5,1,3,  0, 32,3,32,false>(xs2,As2,Ws2,entsS, tpw+32768,  1, 0.f, warp,lane,tid, acc1);
  doPath< 512,4,1,5,  0,128,5,16,false>(xs2,As2,Ws2,entsS, tpw+65536,  2, 0.f, warp,lane,tid, acc2);
  doPath<1024,5,3,1, 32,  0,3,32,false>(xs2,As2,Ws2,entsS, tpw+73728,  3, 0.f, warp,lane,tid, acc1);
  doPath<1024,5,3,3, 32, 32,1,32,false>(xs2,As2,Ws2,entsS, tpw+106496, 4, 0.f, warp,lane,tid, acc0);
  doPath<1024,5,3,3, 32, 32,5,16,false>(xs2,As2,Ws2,entsS, tpw+139264, 5, 0.f, warp,lane,tid, acc2);
  doPath< 512,4,3,5, 32,128,3,32,false>(xs2,As2,Ws2,entsS, tpw+155648, 6, 0.f, warp,lane,tid, acc1);
  doPath< 512,5,5,1,128,  0,5,16,false>(xs2,As2,Ws2,entsS, tpw+172032, 7, 0.f, warp,lane,tid, acc2);
  doPath< 512,5,5,3,128, 32,3,32,false>(xs2,As2,Ws2,entsS, tpw+180224, 8, 0.f, warp,lane,tid, acc1);
  doPath< 256,4,5,5,128,128,1,32,false>(xs2,As2,Ws2,entsS, tpw+196608, 9, 0.f, warp,lane,tid, acc0);
  doPath< 256,4,5,5,128,128,5,16,false>(xs2,As2,Ws2,entsS, tpw+204800,10, 0.f, warp,lane,tid, acc2);

  // ---- linear skip paths: out += einsum('uw,zui->zwi', W, seg)/sqrt(m) ----
  doPath<  32,0,1,1,  0,  0,1,32,true >(xs2,As2,Ws2,entsS, lnw+0,     0, 0.17677669529663689f, warp,lane,tid, acc0);
  doPath<  32,0,3,1, 32,  0,3,32,true >(xs2,As2,Ws2,entsS, lnw+1024,  0, 0.17677669529663689f, warp,lane,tid, acc1);
  doPath<  16,0,5,1,128,  0,5,16,true >(xs2,As2,Ws2,entsS, lnw+2048,  0, 0.25f,                warp,lane,tid, acc2);

  // ---- stage outputs (reuse xs2), then coalesced writeback ----
  #pragma unroll
  for (int ch=0; ch<4; ch++)
    xs2[(warp*4 + ch)*32 + lane] = acc0[ch];
  #pragma unroll
  for (int ch=0; ch<4; ch++)
    #pragma unroll
    for (int k=0;k<3;k++)
      xs2[(32 + (warp*4 + ch)*3 + k)*32 + lane] = acc1[ch*3 + k];
  #pragma unroll
  for (int ch=0; ch<2; ch++)
    #pragma unroll
    for (int k=0;k<5;k++)
      xs2[(128 + (warp*2 + ch)*5 + k)*32 + lane] = acc2[ch*5 + k];
  __syncthreads();

  for (int idx = tid; idx < TN*TOTDIM; idx += NTHREADS){
    int n = idx / TOTDIM, f = idx % TOTDIM;
    out[(node0 + n)*TOTDIM + f] = xf[(f*32 + (n & 31))*2 + (n >> 5)];
  }
}

// ---------------------------------------------------------------------------
extern "C" void kernel_launch(void* const* d_in, const int* in_sizes, int n_in,
                              void* d_out, int out_size)
{
  const float* x   = (const float*)d_in[0];
  const float* tpw = (n_in > 1) ? (const float*)d_in[1] : nullptr;
  const float* lnw = (n_in > 2) ? (const float*)d_in[2] : nullptr;
  for (int i=0;i<n_in;i++){
    if      (in_sizes[i] == NNODES*TOTDIM) x   = (const float*)d_in[i];
    else if (in_sizes[i] == TPWSIZE)       tpw = (const float*)d_in[i];
    else if (in_sizes[i] == LNWSIZE)       lnw = (const float*)d_in[i];
  }

  (void)cudaFuncSetAttribute(mainK, cudaFuncAttributeMaxDynamicSharedMemorySize, SMEM_DYN);
  initK<<<1, 256>>>();
  mainK<<<NBLOCKS, NTHREADS, SMEM_DYN>>>(x, tpw, lnw, (float*)d_out);
}

// round 15
// speedup vs baseline: 3.0017x; 1.7381x over previous
#include <cuda_runtime.h>

// ============================================================================
// HamGNNInspiredNodeBlock: FullyConnectedTensorProduct(x,x) + o3.Linear skip
// irreps = 32x0e + 32x1o + 16x2e  (dims 32 + 96 + 80 = 208), 200000 nodes
// R14: compile-time Wigner-3j (constexpr), packed f32x2 node pairs,
//      uv-split(2) x channel-split(4) accumulate, per-irrep-group output flush.
// ============================================================================

#define NNODES   200000
#define TOTDIM   208
#define TN       64          // nodes per CTA (lane holds nodes lane & lane+32 packed)
#define NTHREADS 256
#define NBLOCKS  (NNODES / TN)   // 3125
#define CU       28          // uv-chunk size
#define TPWSIZE  208896
#define LNWSIZE  2304

// dynamic smem partition (float2 counts)
#define XS2_N (TOTDIM * 32)   // 6656 f2 = 53248 B : x staged [feat][lane], (n, n+32) packed
#define AS2_N (CU * 5 * 32)   // 4480 f2 = 35840 B : A chunk [c][k pad5][lane]
#define WS2_N (CU * 32)       //  896 f2 =  7168 B : W chunk duplicated (w,w)
#define SMEM_DYN ((XS2_N + AS2_N + WS2_N) * 8)   // 96256 B

// ---------------------------------------------------------------------------
// compile-time real-basis Wigner 3j (mirrors e3nn construction exactly)
// ---------------------------------------------------------------------------
struct W3J { int n; int ii[126]; int jj[126]; int kk[126]; float vv[126]; };
struct QM  { double re[5][5]; double im[5][5]; };

constexpr double cabsd(double x){ return x < 0 ? -x : x; }
constexpr double csqrt(double x){
  if (x <= 0.0) return 0.0;
  double g = x > 1.0 ? x : 1.0;
  for (int i = 0; i < 60; i++) g = 0.5*(g + x/g);
  return g;
}

constexpr double ccg(int j1,int m1,int j2,int m2,int j3,int m3){
  if (m1 + m2 != m3) return 0.0;
  double f[8] = {1,1,2,6,24,120,720,5040};
  double pref = csqrt((2.0*j3+1.0)*f[j3+j1-j2]*f[j3-j1+j2]*f[j1+j2-j3]/f[j1+j2+j3+1]);
  pref = pref * csqrt(f[j3+m3]*f[j3-m3]*f[j1-m1]*f[j1+m1]*f[j2-m2]*f[j2+m2]);
  int kmin = 0;
  if (j2-j3-m1 > kmin) kmin = j2-j3-m1;
  if (j1-j3+m2 > kmin) kmin = j1-j3+m2;
  int kmax = j1+j2-j3;
  if (j1-m1 < kmax) kmax = j1-m1;
  if (j2+m2 < kmax) kmax = j2+m2;
  double s = 0.0;
  for (int k = kmin; k <= kmax; k++){
    double d = f[k]*f[j1+j2-j3-k]*f[j1-m1-k]*f[j2+m2-k]*f[j3-j2+m1+k]*f[j3-j1-m2+k];
    s += ((k & 1) ? -1.0 : 1.0)/d;
  }
  return pref*s;
}

constexpr QM cq(int l){
  QM q{};
  double s = csqrt(0.5);
  for (int m = -l; m < 0; m++){ q.re[l+m][l-m] = s; q.im[l+m][l+m] = -s; }
  q.re[l][l] = 1.0;
  for (int m = 1; m <= l; m++){
    double sg = (m & 1) ? -1.0 : 1.0;
    q.re[l+m][l+m] = sg*s;
    q.im[l+m][l-m] = sg*s;
  }
  double pr = 1.0, pi = 0.0;               // (-i)^l
  if ((l & 3) == 1){ pr = 0.0; pi = -1.0; }
  else if ((l & 3) == 2){ pr = -1.0; pi = 0.0; }
  else if ((l & 3) == 3){ pr = 0.0; pi = 1.0; }
  QM o{};
  for (int a = 0; a < 5; a++)
    for (int b = 0; b < 5; b++){
      o.re[a][b] = q.re[a][b]*pr - q.im[a][b]*pi;
      o.im[a][b] = q.re[a][b]*pi + q.im[a][b]*pr;
    }
  return o;
}

constexpr W3J cw3j(int l1, int l2, int l3, int outk){
  QM q1 = cq(l1), q2 = cq(l2), q3 = cq(l3);
  int d1 = 2*l1+1, d2 = 2*l2+1, d3 = 2*l3+1;
  double W[5][5][5] = {};
  for (int i = 0; i < d1; i++)
    for (int j = 0; j < d2; j++)
      for (int k = 0; k < d3; k++){
        double val = 0.0;
        for (int a = 0; a < d1; a++)
          for (int b = 0; b < d2; b++){
            int m1 = a-l1, m2 = b-l2, m3 = m1+m2;
            if (m3 < -l3 || m3 > l3) continue;
            double C = ccg(l1,m1,l2,m2,l3,m3);
            if (C == 0.0) continue;
            int c = m3+l3;
            double tr = q1.re[a][i]*q2.re[b][j] - q1.im[a][i]*q2.im[b][j];
            double ti = q1.re[a][i]*q2.im[b][j] + q1.im[a][i]*q2.re[b][j];
            val += (tr*q3.re[c][k] + ti*q3.im[c][k]) * C;
          }
        W[i][j][k] = val;
      }
  double nrm = 0.0;
  for (int i = 0; i < d1; i++)
    for (int j = 0; j < d2; j++)
      for (int k = 0; k < d3; k++) nrm += W[i][j][k]*W[i][j][k];
  nrm = csqrt(nrm);
  // PATH_COEFF = sqrt((2*l3+1)/FAN); FAN = {2304, 3072, 2304}
  double pc0 = csqrt(1.0/2304.0), pc1 = csqrt(3.0/3072.0), pc2 = csqrt(5.0/2304.0);
  double cf = (outk == 0 ? pc0 : (outk == 1 ? pc1 : pc2)) / nrm;
  W3J t{};
  for (int i = 0; i < d1; i++)
    for (int j = 0; j < d2; j++)
      for (int k = 0; k < d3; k++){
        double v = W[i][j][k];
        if (cabsd(v) > 1e-9*nrm){
          t.ii[t.n] = i; t.jj[t.n] = j; t.kk[t.n] = k;
          t.vv[t.n] = (float)(v*cf); t.n++;
        }
      }
  return t;
}

constexpr W3J TABS[11] = {
  cw3j(0,0,0,0), cw3j(0,1,1,1), cw3j(0,2,2,2), cw3j(1,0,1,1), cw3j(1,1,0,0),
  cw3j(1,1,2,2), cw3j(1,2,1,1), cw3j(2,0,2,2), cw3j(2,1,1,1), cw3j(2,2,0,0),
  cw3j(2,2,2,2)
};

// ---------------------------------------------------------------------------
// packed f32x2 helpers
// ---------------------------------------------------------------------------
union F2U { float2 f; unsigned long long u; };

__device__ __forceinline__ float2 f2fma(float2 a, float2 b, float2 c){
  F2U A, B, C, D; A.f = a; B.f = b; C.f = c;
  asm("fma.rn.f32x2 %0, %1, %2, %3;" : "=l"(D.u) : "l"(A.u), "l"(B.u), "l"(C.u));
  return D.f;
}
__device__ __forceinline__ float2 f2mul(float2 a, float2 b){
  F2U A, B, D; A.f = a; B.f = b;
  asm("mul.rn.f32x2 %0, %1, %2;" : "=l"(D.u) : "l"(A.u), "l"(B.u));
  return D.f;
}

// statically-unrolled CG contraction for one (u,v): all table reads constexpr
template<int PID, int T, int NT>
__device__ __forceinline__ void agenAll(const float2* x1, const float2* x2, float2* a){
  if constexpr (T < NT){
    constexpr int   i = TABS[PID].ii[T];
    constexpr int   j = TABS[PID].jj[T];
    constexpr int   k = TABS[PID].kk[T];
    constexpr float v = TABS[PID].vv[T];
    a[k] = f2fma(f2mul(x1[i], x2[j]), make_float2(v, v), a[k]);
    agenAll<PID, T+1, NT>(x1, x2, a);
  }
}

// ---------------------------------------------------------------------------
// one tensor-product (or linear) path, chunked.
//   A-gen:      warp handles c = warp, warp+8, ...
//   accumulate: warp handles c = ug, ug+2, ...   (ug = warp>>2 : uv half)
//               channels: woBase = (warp&3)*NCHW
// ---------------------------------------------------------------------------
template<int PID,int UVC,int M2SH,int D1,int D2,int OFF1,int OFF2,int KD,int M3,int LIN>
__device__ __forceinline__
void doPath(const float2* __restrict__ xs2, float2* __restrict__ As2,
            float2* __restrict__ Ws2, const float* __restrict__ wsrc,
            float linScale, int warp, int lane, int tid, int ug, int chg,
            float2* __restrict__ acc)
{
  const int NCHW = (M3 == 16) ? 4 : 8;
  const int woBase = chg * NCHW;

  for (int uv0 = 0; uv0 < UVC; uv0 += CU){
    const int cNum = (UVC - uv0 < CU) ? (UVC - uv0) : CU;

    // ---- A-gen ----
    for (int c = warp; c < cNum; c += 8){
      int uv = uv0 + c;
      float2 a[KD];
      if constexpr (LIN){
        #pragma unroll
        for (int k = 0; k < KD; k++){
          float2 t = xs2[(OFF1 + uv*D1 + k)*32 + lane];
          a[k] = make_float2(t.x*linScale, t.y*linScale);
        }
      } else {
        int u = uv >> M2SH;
        int v = uv & ((1 << M2SH) - 1);
        float2 x1[D1], x2[D2];
        const float2* p1 = xs2 + (OFF1 + u*D1)*32 + lane;
        const float2* p2 = xs2 + (OFF2 + v*D2)*32 + lane;
        #pragma unroll
        for (int i = 0; i < D1; i++) x1[i] = p1[i*32];
        #pragma unroll
        for (int j = 0; j < D2; j++) x2[j] = p2[j*32];
        #pragma unroll
        for (int k = 0; k < KD; k++) a[k] = make_float2(0.f, 0.f);
        agenAll<PID, 0, TABS[PID].n>(x1, x2, a);
      }
      #pragma unroll
      for (int k = 0; k < KD; k++) As2[(c*5 + k)*32 + lane] = a[k];
    }

    // ---- W chunk stage, duplicated (w,w) ----
    {
      const float* wp = wsrc + uv0*M3;
      int total = cNum * M3;
      for (int idx = tid; idx < total; idx += NTHREADS){
        float w = wp[idx];
        Ws2[idx] = make_float2(w, w);
      }
    }
    __syncthreads();

    // ---- accumulate: uv half x channel quarter ----
    #pragma unroll 2
    for (int c = ug; c < cNum; c += 2){
      float2 av[KD];
      #pragma unroll
      for (int k = 0; k < KD; k++) av[k] = As2[(c*5 + k)*32 + lane];
      const float4* w4 = (const float4*)(Ws2 + c*M3 + woBase);
      #pragma unroll
      for (int cp = 0; cp < NCHW/2; cp++){
        float4 wq = w4[cp];
        float2 wa = make_float2(wq.x, wq.y);
        float2 wb = make_float2(wq.z, wq.w);
        #pragma unroll
        for (int k = 0; k < KD; k++){
          acc[(2*cp  )*KD + k] = f2fma(av[k], wa, acc[(2*cp  )*KD + k]);
          acc[(2*cp+1)*KD + k] = f2fma(av[k], wb, acc[(2*cp+1)*KD + k]);
        }
      }
    }
    __syncthreads();
  }
}

// ---------------------------------------------------------------------------
// group flush: two-phase uv-half reduce into padded smem rows, coalesced STG
// ---------------------------------------------------------------------------
template<int GF, int KD, int GOFF>
__device__ __forceinline__
void flushGroup(const float2* __restrict__ acc, float* __restrict__ fbuf,
                float* __restrict__ outp, int node0,
                int lane, int tid, int ug, int chg)
{
  const int FP   = GF + 1;                 // odd pad -> conflict-free rows
  const int NCHW = (KD == 5) ? 4 : 8;
  const int woBase = chg * NCHW;

  if (ug == 0){
    #pragma unroll
    for (int ch = 0; ch < NCHW; ch++)
      #pragma unroll
      for (int k = 0; k < KD; k++){
        int f = (woBase + ch)*KD + k;
        float2 v = acc[ch*KD + k];
        fbuf[ lane      *FP + f] = v.x;
        fbuf[(lane + 32)*FP + f] = v.y;
      }
  }
  __syncthreads();
  if (ug == 1){
    #pragma unroll
    for (int ch = 0; ch < NCHW; ch++)
      #pragma unroll
      for (int k = 0; k < KD; k++){
        int f = (woBase + ch)*KD + k;
        float2 v = acc[ch*KD + k];
        fbuf[ lane      *FP + f] += v.x;
        fbuf[(lane + 32)*FP + f] += v.y;
      }
  }
  __syncthreads();
  for (int idx = tid; idx < 64*GF; idx += NTHREADS){
    int f = idx % GF, n = idx / GF;
    outp[(node0 + n)*TOTDIM + GOFF + f] = fbuf[n*FP + f];
  }
  __syncthreads();   // fbuf (As region) reused by next group
}

// ---------------------------------------------------------------------------
__global__ void __launch_bounds__(NTHREADS, 2)
mainK(const float* __restrict__ x, const float* __restrict__ tpw,
      const float* __restrict__ lnw, float* __restrict__ out)
{
  extern __shared__ char smRaw[];
  float2* xs2 = (float2*)smRaw;            // [feat][lane] packed node pairs
  float2* As2 = xs2 + XS2_N;
  float2* Ws2 = As2 + AS2_N;
  float*  fbuf = (float*)As2;              // group flush buffer (reuses As)

  int tid  = threadIdx.x;
  int lane = tid & 31;
  int warp = tid >> 5;
  int ug   = warp >> 2;                    // uv half
  int chg  = warp & 3;                     // channel quarter
  int node0 = blockIdx.x * TN;

  // stage x packed: lane-fast node mapping -> conflict-free STS (scattered LDG,
  // DRAM has huge headroom at 0.3%)
  float* xf = (float*)xs2;
  for (int idx = tid; idx < TN*TOTDIM; idx += NTHREADS){
    int n = idx & 63, f = idx >> 6;
    xf[(f*32 + (n & 31))*2 + (n >> 5)] = x[(node0 + n)*TOTDIM + f];
  }
  __syncthreads();

  const float LS01 = 0.17677669529663689f;  // 1/sqrt(32)
  const float LS2  = 0.25f;                 // 1/sqrt(16)

  // ================= group 0 : output irrep 0 (32x0e, dims [0,32)) ==========
  {
    float2 acc[8];
    #pragma unroll
    for (int i = 0; i < 8; i++) acc[i] = make_float2(0.f, 0.f);
    //     PID  UVC M2SH D1 D2 OFF1 OFF2 KD M3 LIN
    doPath<0, 1024, 5, 1, 1,   0,   0, 1, 32, 0>(xs2, As2, Ws2, tpw+0,      0.f, warp, lane, tid, ug, chg, acc);
    doPath<4, 1024, 5, 3, 3,  32,  32, 1, 32, 0>(xs2, As2, Ws2, tpw+106496, 0.f, warp, lane, tid, ug, chg, acc);
    doPath<9,  256, 4, 5, 5, 128, 128, 1, 32, 0>(xs2, As2, Ws2, tpw+196608, 0.f, warp, lane, tid, ug, chg, acc);
    doPath<0,   32, 0, 1, 1,   0,   0, 1, 32, 1>(xs2, As2, Ws2, lnw+0,     LS01, warp, lane, tid, ug, chg, acc);
    flushGroup<32, 1, 0>(acc, fbuf, out, node0, lane, tid, ug, chg);
  }

  // ================= group 1 : output irrep 1 (32x1o, dims [32,128)) ========
  {
    float2 acc[24];
    #pragma unroll
    for (int i = 0; i < 24; i++) acc[i] = make_float2(0.f, 0.f);
    doPath<1, 1024, 5, 1, 3,   0,  32, 3, 32, 0>(xs2, As2, Ws2, tpw+32768,  0.f, warp, lane, tid, ug, chg, acc);
    doPath<3, 1024, 5, 3, 1,  32,   0, 3, 32, 0>(xs2, As2, Ws2, tpw+73728,  0.f, warp, lane, tid, ug, chg, acc);
    doPath<6,  512, 4, 3, 5,  32, 128, 3, 32, 0>(xs2, As2, Ws2, tpw+155648, 0.f, warp, lane, tid, ug, chg, acc);
    doPath<8,  512, 5, 5, 3, 128,  32, 3, 32, 0>(xs2, As2, Ws2, tpw+180224, 0.f, warp, lane, tid, ug, chg, acc);
    doPath<0,   32, 0, 3, 1,  32,   0, 3, 32, 1>(xs2, As2, Ws2, lnw+1024,  LS01, warp, lane, tid, ug, chg, acc);
    flushGroup<96, 3, 32>(acc, fbuf, out, node0, lane, tid, ug, chg);
  }

  // ================= group 2 : output irrep 2 (16x2e, dims [128,208)) =======
  {
    float2 acc[20];
    #pragma unroll
    for (int i = 0; i < 20; i++) acc[i] = make_float2(0.f, 0.f);
    doPath< 2,  512, 4, 1, 5,   0, 128, 5, 16, 0>(xs2, As2, Ws2, tpw+65536,  0.f, warp, lane, tid, ug, chg, acc);
    doPath< 5, 1024, 5, 3, 3,  32,  32, 5, 16, 0>(xs2, As2, Ws2, tpw+139264, 0.f, warp, lane, tid, ug, chg, acc);
    doPath< 7,  512, 5, 5, 1, 128,   0, 5, 16, 0>(xs2, As2, Ws2, tpw+172032, 0.f, warp, lane, tid, ug, chg, acc);
    doPath<10,  256, 4, 5, 5, 128, 128, 5, 16, 0>(xs2, As2, Ws2, tpw+204800, 0.f, warp, lane, tid, ug, chg, acc);
    doPath< 0,   16, 0, 5, 1, 128,   0, 5, 16, 1>(xs2, As2, Ws2, lnw+2048,   LS2, warp, lane, tid, ug, chg, acc);
    flushGroup<80, 5, 128>(acc, fbuf, out, node0, lane, tid, ug, chg);
  }
}

// ---------------------------------------------------------------------------
extern "C" void kernel_launch(void* const* d_in, const int* in_sizes, int n_in,
                              void* d_out, int out_size)
{
  const float* x   = (const float*)d_in[0];
  const float* tpw = (n_in > 1) ? (const float*)d_in[1] : nullptr;
  const float* lnw = (n_in > 2) ? (const float*)d_in[2] : nullptr;
  for (int i = 0; i < n_in; i++){
    if      (in_sizes[i] == NNODES*TOTDIM) x   = (const float*)d_in[i];
    else if (in_sizes[i] == TPWSIZE)       tpw = (const float*)d_in[i];
    else if (in_sizes[i] == LNWSIZE)       lnw = (const float*)d_in[i];
  }

  (void)cudaFuncSetAttribute(mainK, cudaFuncAttributeMaxDynamicSharedMemorySize, SMEM_DYN);
  mainK<<<NBLOCKS, NTHREADS, SMEM_DYN>>>(x, tpw, lnw, (float*)d_out);
}

// round 16
// speedup vs baseline: 3.1515x; 1.0499x over previous
#include <cuda_runtime.h>

// ============================================================================
// HamGNNInspiredNodeBlock: FullyConnectedTensorProduct(x,x) + o3.Linear skip
// irreps = 32x0e + 32x1o + 16x2e  (dims 32 + 96 + 80 = 208), 200000 nodes
// R15: software-pipelined chunks (CU=16, double buffer, 1 sync/chunk),
//      chunk-constant-u A-gen hoist, group-2 k-split accumulate.
// ============================================================================

#define NNODES   200000
#define TOTDIM   208
#define TN       64          // nodes per CTA (lane holds nodes lane & lane+32 packed)
#define NTHREADS 256
#define NBLOCKS  (NNODES / TN)   // 3125
#define CU       16          // uv-chunk size (divides every UVC exactly)
#define TPWSIZE  208896
#define LNWSIZE  2304

// dynamic smem partition (float2 counts)
#define XS2_N (TOTDIM * 32)     // 6656 f2 = 53248 B : x staged [feat][lane]
#define AS2_N (2 * CU * 5 * 32) // 5120 f2 = 40960 B : A double buffer
#define WS2_N (2 * CU * 32)     // 1024 f2 =  8192 B : W double buffer (w,w)
#define AS_STRIDE (CU * 5 * 32) // 2560 f2 per buffer
#define WS_STRIDE (CU * 32)     //  512 f2 per buffer
#define SMEM_DYN ((XS2_N + AS2_N + WS2_N) * 8)   // 102400 B

// ---------------------------------------------------------------------------
// compile-time real-basis Wigner 3j (mirrors e3nn construction exactly)
// ---------------------------------------------------------------------------
struct W3J { int n; int ii[126]; int jj[126]; int kk[126]; float vv[126]; };
struct QM  { double re[5][5]; double im[5][5]; };

constexpr double cabsd(double x){ return x < 0 ? -x : x; }
constexpr double csqrt(double x){
  if (x <= 0.0) return 0.0;
  double g = x > 1.0 ? x : 1.0;
  for (int i = 0; i < 60; i++) g = 0.5*(g + x/g);
  return g;
}

constexpr double ccg(int j1,int m1,int j2,int m2,int j3,int m3){
  if (m1 + m2 != m3) return 0.0;
  double f[8] = {1,1,2,6,24,120,720,5040};
  double pref = csqrt((2.0*j3+1.0)*f[j3+j1-j2]*f[j3-j1+j2]*f[j1+j2-j3]/f[j1+j2+j3+1]);
  pref = pref * csqrt(f[j3+m3]*f[j3-m3]*f[j1-m1]*f[j1+m1]*f[j2-m2]*f[j2+m2]);
  int kmin = 0;
  if (j2-j3-m1 > kmin) kmin = j2-j3-m1;
  if (j1-j3+m2 > kmin) kmin = j1-j3+m2;
  int kmax = j1+j2-j3;
  if (j1-m1 < kmax) kmax = j1-m1;
  if (j2+m2 < kmax) kmax = j2+m2;
  double s = 0.0;
  for (int k = kmin; k <= kmax; k++){
    double d = f[k]*f[j1+j2-j3-k]*f[j1-m1-k]*f[j2+m2-k]*f[j3-j2+m1+k]*f[j3-j1-m2+k];
    s += ((k & 1) ? -1.0 : 1.0)/d;
  }
  return pref*s;
}

constexpr QM cq(int l){
  QM q{};
  double s = csqrt(0.5);
  for (int m = -l; m < 0; m++){ q.re[l+m][l-m] = s; q.im[l+m][l+m] = -s; }
  q.re[l][l] = 1.0;
  for (int m = 1; m <= l; m++){
    double sg = (m & 1) ? -1.0 : 1.0;
    q.re[l+m][l+m] = sg*s;
    q.im[l+m][l-m] = sg*s;
  }
  double pr = 1.0, pi = 0.0;               // (-i)^l
  if ((l & 3) == 1){ pr = 0.0; pi = -1.0; }
  else if ((l & 3) == 2){ pr = -1.0; pi = 0.0; }
  else if ((l & 3) == 3){ pr = 0.0; pi = 1.0; }
  QM o{};
  for (int a = 0; a < 5; a++)
    for (int b = 0; b < 5; b++){
      o.re[a][b] = q.re[a][b]*pr - q.im[a][b]*pi;
      o.im[a][b] = q.re[a][b]*pi + q.im[a][b]*pr;
    }
  return o;
}

constexpr W3J cw3j(int l1, int l2, int l3, int outk){
  QM q1 = cq(l1), q2 = cq(l2), q3 = cq(l3);
  int d1 = 2*l1+1, d2 = 2*l2+1, d3 = 2*l3+1;
  double W[5][5][5] = {};
  for (int i = 0; i < d1; i++)
    for (int j = 0; j < d2; j++)
      for (int k = 0; k < d3; k++){
        double val = 0.0;
        for (int a = 0; a < d1; a++)
          for (int b = 0; b < d2; b++){
            int m1 = a-l1, m2 = b-l2, m3 = m1+m2;
            if (m3 < -l3 || m3 > l3) continue;
            double C = ccg(l1,m1,l2,m2,l3,m3);
            if (C == 0.0) continue;
            int c = m3+l3;
            double tr = q1.re[a][i]*q2.re[b][j] - q1.im[a][i]*q2.im[b][j];
            double ti = q1.re[a][i]*q2.im[b][j] + q1.im[a][i]*q2.re[b][j];
            val += (tr*q3.re[c][k] + ti*q3.im[c][k]) * C;
          }
        W[i][j][k] = val;
      }
  double nrm = 0.0;
  for (int i = 0; i < d1; i++)
    for (int j = 0; j < d2; j++)
      for (int k = 0; k < d3; k++) nrm += W[i][j][k]*W[i][j][k];
  nrm = csqrt(nrm);
  // PATH_COEFF = sqrt((2*l3+1)/FAN); FAN = {2304, 3072, 2304}
  double pc0 = csqrt(1.0/2304.0), pc1 = csqrt(3.0/3072.0), pc2 = csqrt(5.0/2304.0);
  double cf = (outk == 0 ? pc0 : (outk == 1 ? pc1 : pc2)) / nrm;
  W3J t{};
  for (int i = 0; i < d1; i++)
    for (int j = 0; j < d2; j++)
      for (int k = 0; k < d3; k++){
        double v = W[i][j][k];
        if (cabsd(v) > 1e-9*nrm){
          t.ii[t.n] = i; t.jj[t.n] = j; t.kk[t.n] = k;
          t.vv[t.n] = (float)(v*cf); t.n++;
        }
      }
  return t;
}

constexpr W3J TABS[11] = {
  cw3j(0,0,0,0), cw3j(0,1,1,1), cw3j(0,2,2,2), cw3j(1,0,1,1), cw3j(1,1,0,0),
  cw3j(1,1,2,2), cw3j(1,2,1,1), cw3j(2,0,2,2), cw3j(2,1,1,1), cw3j(2,2,0,0),
  cw3j(2,2,2,2)
};

// ---------------------------------------------------------------------------
// packed f32x2 helpers
// ---------------------------------------------------------------------------
union F2U { float2 f; unsigned long long u; };

__device__ __forceinline__ float2 f2fma(float2 a, float2 b, float2 c){
  F2U A, B, C, D; A.f = a; B.f = b; C.f = c;
  asm("fma.rn.f32x2 %0, %1, %2, %3;" : "=l"(D.u) : "l"(A.u), "l"(B.u), "l"(C.u));
  return D.f;
}
__device__ __forceinline__ float2 f2mul(float2 a, float2 b){
  F2U A, B, D; A.f = a; B.f = b;
  asm("mul.rn.f32x2 %0, %1, %2;" : "=l"(D.u) : "l"(A.u), "l"(B.u));
  return D.f;
}

// statically-unrolled CG contraction for one (u,v): all table reads constexpr
template<int PID, int T, int NT>
__device__ __forceinline__ void agenAll(const float2* x1, const float2* x2, float2* a){
  if constexpr (T < NT){
    constexpr int   i = TABS[PID].ii[T];
    constexpr int   j = TABS[PID].jj[T];
    constexpr int   k = TABS[PID].kk[T];
    constexpr float v = TABS[PID].vv[T];
    a[k] = f2fma(f2mul(x1[i], x2[j]), make_float2(v, v), a[k]);
    agenAll<PID, T+1, NT>(x1, x2, a);
  }
}

// ---------------------------------------------------------------------------
// accumulate one chunk: c = ug, ug+2, ...; channels [woBase, woBase+NCHW);
// k range [KB, KB+KN) of KDTOT, acc stride ASTR.
// ---------------------------------------------------------------------------
template<int KN, int KB, int NCHW, int ASTR, int M3>
__device__ __forceinline__
void accumChunk(const float2* __restrict__ As, const float2* __restrict__ Ws,
                int ug, int woBase, int lane, float2* __restrict__ acc)
{
  #pragma unroll 2
  for (int c = ug; c < CU; c += 2){
    float2 av[KN];
    #pragma unroll
    for (int k = 0; k < KN; k++) av[k] = As[(c*5 + KB + k)*32 + lane];
    const float4* w4 = (const float4*)(Ws + c*M3 + woBase);
    #pragma unroll
    for (int cp = 0; cp < NCHW/2; cp++){
      float4 wq = w4[cp];
      float2 wa = make_float2(wq.x, wq.y);
      float2 wb = make_float2(wq.z, wq.w);
      #pragma unroll
      for (int k = 0; k < KN; k++){
        acc[(2*cp  )*ASTR + k] = f2fma(av[k], wa, acc[(2*cp  )*ASTR + k]);
        acc[(2*cp+1)*ASTR + k] = f2fma(av[k], wb, acc[(2*cp+1)*ASTR + k]);
      }
    }
  }
}

// ---------------------------------------------------------------------------
// one path, software-pipelined over chunks (double-buffered A and W)
//   gen:        warp handles c = 2*warp, 2*warp+1 (u is chunk-constant)
//   accumulate: KSPL=0: ug=warp>>2, chg=warp&3 (NCHW=M3/4)
//               KSPL=1: ug=warp>>2, chg=(warp>>1)&1, kh=warp&1 (NCHW=M3/2)
// ---------------------------------------------------------------------------
template<int PID,int UVC,int M2SH,int D1,int D2,int OFF1,int OFF2,int KD,int M3,
         int LIN,int KSPL>
__device__ __forceinline__
void doPath(const float2* __restrict__ xs2, float2* __restrict__ AsB,
            float2* __restrict__ WsB, const float* __restrict__ wsrc,
            float linScale, int warp, int lane, int tid,
            float2* __restrict__ acc)
{
  const int M2  = 1 << M2SH;
  const int nCh = UVC / CU;
  const int ug  = warp >> 2;
  const int kh  = warp & 1;

  int woBase;
  if constexpr (KSPL) woBase = ((warp >> 1) & 1) * (M3/2);
  else                woBase = (warp & 3) * (M3/4);

  auto gen = [&](int t, float2* As, float2* Ws){
    int uv0 = t * CU;
    // W stage (duplicated (w,w)); CU*M3 is 256 or 512
    {
      const float* wp = wsrc + uv0*M3;
      #pragma unroll
      for (int r = 0; r < (CU*M3 + NTHREADS - 1)/NTHREADS; r++){
        int idx = tid + r*NTHREADS;
        if ((CU*M3 % NTHREADS == 0) || idx < CU*M3){
          float w = wp[idx];
          Ws[idx] = make_float2(w, w);
        }
      }
    }
    if constexpr (LIN){
      #pragma unroll
      for (int s = 0; s < 2; s++){
        int c = 2*warp + s;
        int uv = uv0 + c;
        #pragma unroll
        for (int k = 0; k < KD; k++){
          float2 v = xs2[(OFF1 + uv*D1 + k)*32 + lane];
          As[(c*5 + k)*32 + lane] = make_float2(v.x*linScale, v.y*linScale);
        }
      }
    } else {
      // u constant across the whole chunk (CU=16 divides M2)
      int u  = uv0 >> M2SH;
      int v0 = uv0 & (M2 - 1);
      float2 x1[D1];
      const float2* p1 = xs2 + (OFF1 + u*D1)*32 + lane;
      #pragma unroll
      for (int i = 0; i < D1; i++) x1[i] = p1[i*32];
      #pragma unroll
      for (int s = 0; s < 2; s++){
        int c = 2*warp + s;
        int v = v0 + c;
        float2 x2[D2];
        const float2* p2 = xs2 + (OFF2 + v*D2)*32 + lane;
        #pragma unroll
        for (int j = 0; j < D2; j++) x2[j] = p2[j*32];
        float2 a[KD];
        #pragma unroll
        for (int k = 0; k < KD; k++) a[k] = make_float2(0.f, 0.f);
        agenAll<PID, 0, TABS[PID].n>(x1, x2, a);
        #pragma unroll
        for (int k = 0; k < KD; k++) As[(c*5 + k)*32 + lane] = a[k];
      }
    }
  };

  auto accum = [&](int b){
    const float2* As = AsB + b*AS_STRIDE;
    const float2* Ws = WsB + b*WS_STRIDE;
    if constexpr (KSPL){
      // KD==5: k 0-2 on kh=0 warps, k 3-4 on kh=1 warps; acc stride 3
      if (kh) accumChunk<2, 3, M3/2, 3, M3>(As, Ws, ug, woBase, lane, acc);
      else    accumChunk<3, 0, M3/2, 3, M3>(As, Ws, ug, woBase, lane, acc);
    } else {
      accumChunk<KD, 0, M3/4, KD, M3>(As, Ws, ug, woBase, lane, acc);
    }
  };

  gen(0, AsB, WsB);
  __syncthreads();
  for (int t = 1; t < nCh; t++){
    int b = t & 1;
    gen(t, AsB + b*AS_STRIDE, WsB + b*WS_STRIDE);
    accum((t-1) & 1);
    __syncthreads();
  }
  accum((nCh-1) & 1);
  __syncthreads();
}

// ---------------------------------------------------------------------------
// group flush: two-phase uv-half reduce into padded smem rows, coalesced STG
// f = (woBase+ch)*KDTOT + KB + k  for ch<NCHW, k<KN (disjoint across warps/ug)
// ---------------------------------------------------------------------------
template<int GF, int GOFF>
__device__ __forceinline__
void flushGroup(const float2* __restrict__ acc, float* __restrict__ fbuf,
                float* __restrict__ outp, int node0, int lane, int tid,
                int ug, int woBase, int nchw, int kdtot, int kb, int kn, int astr)
{
  const int FP = GF + 1;                 // odd pad -> conflict-free rows
  if (ug == 0){
    for (int ch = 0; ch < nchw; ch++)
      for (int k = 0; k < kn; k++){
        int f = (woBase + ch)*kdtot + kb + k;
        float2 v = acc[ch*astr + k];
        fbuf[ lane      *FP + f] = v.x;
        fbuf[(lane + 32)*FP + f] = v.y;
      }
  }
  __syncthreads();
  if (ug == 1){
    for (int ch = 0; ch < nchw; ch++)
      for (int k = 0; k < kn; k++){
        int f = (woBase + ch)*kdtot + kb + k;
        float2 v = acc[ch*astr + k];
        fbuf[ lane      *FP + f] += v.x;
        fbuf[(lane + 32)*FP + f] += v.y;
      }
  }
  __syncthreads();
  for (int idx = tid; idx < 64*GF; idx += NTHREADS){
    int f = idx % GF, n = idx / GF;
    outp[(node0 + n)*TOTDIM + GOFF + f] = fbuf[n*FP + f];
  }
  __syncthreads();   // fbuf (As region) reused by next group
}

// ---------------------------------------------------------------------------
__global__ void __launch_bounds__(NTHREADS, 2)
mainK(const float* __restrict__ x, const float* __restrict__ tpw,
      const float* __restrict__ lnw, float* __restrict__ out)
{
  extern __shared__ char smRaw[];
  float2* xs2 = (float2*)smRaw;            // [feat][lane] packed node pairs
  float2* AsB = xs2 + XS2_N;               // A double buffer
  float2* WsB = AsB + AS2_N;               // W double buffer
  float*  fbuf = (float*)AsB;              // group flush buffer (reuses As)

  int tid  = threadIdx.x;
  int lane = tid & 31;
  int warp = tid >> 5;
  int ug   = warp >> 2;
  int node0 = blockIdx.x * TN;

  // stage x packed: lane-fast node mapping -> conflict-free STS
  float* xf = (float*)xs2;
  for (int idx = tid; idx < TN*TOTDIM; idx += NTHREADS){
    int n = idx & 63, f = idx >> 6;
    xf[(f*32 + (n & 31))*2 + (n >> 5)] = x[(node0 + n)*TOTDIM + f];
  }
  __syncthreads();

  const float LS01 = 0.17677669529663689f;  // 1/sqrt(32)
  const float LS2  = 0.25f;                 // 1/sqrt(16)

  // ================= group 0 : output irrep 0 (32x0e, dims [0,32)) ==========
  {
    float2 acc[8];
    #pragma unroll
    for (int i = 0; i < 8; i++) acc[i] = make_float2(0.f, 0.f);
    //     PID  UVC M2SH D1 D2 OFF1 OFF2 KD M3 LIN KSPL
    doPath<0, 1024, 5, 1, 1,   0,   0, 1, 32, 0, 0>(xs2, AsB, WsB, tpw+0,      0.f, warp, lane, tid, acc);
    doPath<4, 1024, 5, 3, 3,  32,  32, 1, 32, 0, 0>(xs2, AsB, WsB, tpw+106496, 0.f, warp, lane, tid, acc);
    doPath<9,  256, 4, 5, 5, 128, 128, 1, 32, 0, 0>(xs2, AsB, WsB, tpw+196608, 0.f, warp, lane, tid, acc);
    doPath<0,   32, 0, 1, 1,   0,   0, 1, 32, 1, 0>(xs2, AsB, WsB, lnw+0,     LS01, warp, lane, tid, acc);
    flushGroup<32, 0>(acc, fbuf, out, node0, lane, tid, ug, (warp&3)*8, 8, 1, 0, 1, 1);
  }

  // ================= group 1 : output irrep 1 (32x1o, dims [32,128)) ========
  {
    float2 acc[24];
    #pragma unroll
    for (int i = 0; i < 24; i++) acc[i] = make_float2(0.f, 0.f);
    doPath<1, 1024, 5, 1, 3,   0,  32, 3, 32, 0, 0>(xs2, AsB, WsB, tpw+32768,  0.f, warp, lane, tid, acc);
    doPath<3, 1024, 5, 3, 1,  32,   0, 3, 32, 0, 0>(xs2, AsB, WsB, tpw+73728,  0.f, warp, lane, tid, acc);
    doPath<6,  512, 4, 3, 5,  32, 128, 3, 32, 0, 0>(xs2, AsB, WsB, tpw+155648, 0.f, warp, lane, tid, acc);
    doPath<8,  512, 5, 5, 3, 128,  32, 3, 32, 0, 0>(xs2, AsB, WsB, tpw+180224, 0.f, warp, lane, tid, acc);
    doPath<0,   32, 0, 3, 1,  32,   0, 3, 32, 1, 0>(xs2, AsB, WsB, lnw+1024,  LS01, warp, lane, tid, acc);
    flushGroup<96, 32>(acc, fbuf, out, node0, lane, tid, ug, (warp&3)*8, 8, 3, 0, 3, 3);
  }

  // ================= group 2 : output irrep 2 (16x2e, dims [128,208)) =======
  // k-split accumulate: warps = uv2 x ch2 x k{0-2 | 3-4}
  {
    float2 acc[24];
    #pragma unroll
    for (int i = 0; i < 24; i++) acc[i] = make_float2(0.f, 0.f);
    doPath< 2,  512, 4, 1, 5,   0, 128, 5, 16, 0, 1>(xs2, AsB, WsB, tpw+65536,  0.f, warp, lane, tid, acc);
    doPath< 5, 1024, 5, 3, 3,  32,  32, 5, 16, 0, 1>(xs2, AsB, WsB, tpw+139264, 0.f, warp, lane, tid, acc);
    doPath< 7,  512, 5, 5, 1, 128,   0, 5, 16, 0, 1>(xs2, AsB, WsB, tpw+172032, 0.f, warp, lane, tid, acc);
    doPath<10,  256, 4, 5, 5, 128, 128, 5, 16, 0, 1>(xs2, AsB, WsB, tpw+204800, 0.f, warp, lane, tid, acc);
    doPath< 0,   16, 0, 5, 1, 128,   0, 5, 16, 1, 1>(xs2, AsB, WsB, lnw+2048,   LS2, warp, lane, tid, acc);
    int kh = warp & 1;
    flushGroup<80, 128>(acc, fbuf, out, node0, lane, tid, ug,
                        ((warp>>1)&1)*8, 8, 5, kh ? 3 : 0, kh ? 2 : 3, 3);
  }
}

// ---------------------------------------------------------------------------
extern "C" void kernel_launch(void* const* d_in, const int* in_sizes, int n_in,
                              void* d_out, int out_size)
{
  const float* x   = (const float*)d_in[0];
  const float* tpw = (n_in > 1) ? (const float*)d_in[1] : nullptr;
  const float* lnw = (n_in > 2) ? (const float*)d_in[2] : nullptr;
  for (int i = 0; i < n_in; i++){
    if      (in_sizes[i] == NNODES*TOTDIM) x   = (const float*)d_in[i];
    else if (in_sizes[i] == TPWSIZE)       tpw = (const float*)d_in[i];
    else if (in_sizes[i] == LNWSIZE)       lnw = (const float*)d_in[i];
  }

  (void)cudaFuncSetAttribute(mainK, cudaFuncAttributeMaxDynamicSharedMemorySize, SMEM_DYN);
  mainK<<<NBLOCKS, NTHREADS, SMEM_DYN>>>(x, tpw, lnw, (float*)d_out);
}